// round 17
// baseline (speedup 1.0000x reference)
#include <cuda_runtime.h>
#include <cuda_fp16.h>
#include <cstdint>

#define N_FEATS 9
#define VOCAB   119
#define HIDDEN  128
#define MAXN    50176
#define TILE_M  128
#define HSTR2   136      // padded smem stride for fp16 h tile (halves)

// Scratch (no allocations allowed).
__device__ __half g_qh[MAXN * HIDDEN];
__device__ __half g_kh[MAXN * HIDDEN];
__device__ __half g_vh[MAXN * HIDDEN];
// W pre-packed into fp16 mma B-fragment order:
// [3 g][8 np][8 kc][32 lane] uint4 = {b0(n0),b1(n0),b0(n1),b1(n1)} half2s
__device__ uint4  g_wbh[3 * 8 * 8 * 32];
__device__ int    g_mask_i32;

__device__ __forceinline__ void mma_f16(float d[4], const uint32_t a[4],
                                        uint32_t b0, uint32_t b1) {
    asm volatile(
        "mma.sync.aligned.m16n8k16.row.col.f32.f16.f16.f32 "
        "{%0,%1,%2,%3}, {%4,%5,%6,%7}, {%8,%9}, {%0,%1,%2,%3};"
        : "+f"(d[0]), "+f"(d[1]), "+f"(d[2]), "+f"(d[3])
        : "r"(a[0]), "r"(a[1]), "r"(a[2]), "r"(a[3]), "r"(b0), "r"(b1));
}

__device__ __forceinline__ uint32_t h2_as_u32(__half2 h) {
    return *reinterpret_cast<uint32_t*>(&h);
}

// ---------------------------------------------------------------------------
// Prep: pack W (fp16) into m16n8k16 B-fragment order + detect mask dtype.
//   b0(n) = half2(W[kr][n],   W[kr+1][n]),  kr = kc*16 + (lane&3)*2
//   b1(n) = half2(W[kr+8][n], W[kr+9][n])
//   n0 = np*16 + (lane>>2), n1 = n0 + 8
// ---------------------------------------------------------------------------
__global__ __launch_bounds__(512) void k_prep(
    const float* __restrict__ Wq, const float* __restrict__ Wk,
    const float* __restrict__ Wv, const unsigned char* __restrict__ mask)
{
    const int bid = blockIdx.x;
    if (bid < 12) {
        const int i    = bid * 512 + threadIdx.x;   // 0..6143
        const int lane = i & 31;
        const int kc   = (i >> 5) & 7;
        const int np   = (i >> 8) & 7;
        const int g    = i >> 11;
        const float* W = (g == 0) ? Wq : (g == 1) ? Wk : Wv;
        const int kr = kc * 16 + (lane & 3) * 2;
        const int n0 = np * 16 + (lane >> 2);
        const int n1 = n0 + 8;
        uint4 u;
        u.x = h2_as_u32(__floats2half2_rn(W[kr * 128 + n0],       W[(kr + 1) * 128 + n0]));
        u.y = h2_as_u32(__floats2half2_rn(W[(kr + 8) * 128 + n0], W[(kr + 9) * 128 + n0]));
        u.z = h2_as_u32(__floats2half2_rn(W[kr * 128 + n1],       W[(kr + 1) * 128 + n1]));
        u.w = h2_as_u32(__floats2half2_rn(W[(kr + 8) * 128 + n1], W[(kr + 9) * 128 + n1]));
        g_wbh[i] = u;
    } else {
        int ok = 1;
        for (int gi = threadIdx.x; gi < 1024; gi += 512)
            if (mask[gi * 4 + 1] | mask[gi * 4 + 2] | mask[gi * 4 + 3]) ok = 0;
        ok = __syncthreads_and(ok);
        if (threadIdx.x == 0) g_mask_i32 = ok;
    }
}

// ---------------------------------------------------------------------------
// Encode: AtomEncoder + 3x fp16 mma.sync GEMM (f32 accum). 128 nodes/CTA,
// 256 threads. h tile stored fp16 in smem (~40KB); W fragments stream from
// g_wbh via coalesced LDG.128.
// ---------------------------------------------------------------------------
__global__ __launch_bounds__(256) void k_encode_qkv(
    const int*   __restrict__ X,
    const float* __restrict__ emb,
    const float* __restrict__ bq, const float* __restrict__ bk,
    const float* __restrict__ bv, int N)
{
    extern __shared__ __align__(16) char smem_raw[];
    __half* sh_h = reinterpret_cast<__half*>(smem_raw);          // [128][HSTR2]
    int*    sh_x = reinterpret_cast<int*>(smem_raw + TILE_M * HSTR2 * 2);

    const int tid   = threadIdx.x;
    const int node0 = blockIdx.x * TILE_M;

    for (int i = tid; i < TILE_M * N_FEATS; i += 256) {
        const int node = min(node0 + i / N_FEATS, N - 1);
        sh_x[i] = X[node * N_FEATS + (i % N_FEATS)];
    }
    __syncthreads();

    // h = sum of 9 embedding rows; store fp16 (2x half2 = uint2 per 4 cols).
    for (int gi = tid; gi < TILE_M * 32; gi += 256) {
        const int node = gi >> 5;
        const int c0   = (gi & 31) * 4;
        float4 s = make_float4(0.f, 0.f, 0.f, 0.f);
#pragma unroll
        for (int f = 0; f < N_FEATS; f++) {
            const int x = sh_x[node * N_FEATS + f];
            const float4 e = *reinterpret_cast<const float4*>(
                &emb[(f * VOCAB + x) * HIDDEN + c0]);
            s.x += e.x; s.y += e.y; s.z += e.z; s.w += e.w;
        }
        uint2 u;
        u.x = h2_as_u32(__floats2half2_rn(s.x, s.y));
        u.y = h2_as_u32(__floats2half2_rn(s.z, s.w));
        *reinterpret_cast<uint2*>(&sh_h[node * HSTR2 + c0]) = u;
    }
    __syncthreads();

    // A fragments: 8 k-chunks (k=16 each) x 4 regs (half2-packed).
    const int warp = tid >> 5;
    const int lane = tid & 31;
    const int m0   = warp * 16;
    const int ar   = m0 + (lane >> 2);
    const int ac   = (lane & 3) * 2;

    uint32_t afrag[32];
#pragma unroll
    for (int kc = 0; kc < 8; kc++) {
        const int base = ar * HSTR2 + kc * 16 + ac;
        afrag[kc * 4 + 0] = *reinterpret_cast<const uint32_t*>(&sh_h[base]);
        afrag[kc * 4 + 1] = *reinterpret_cast<const uint32_t*>(&sh_h[base + 8 * HSTR2]);
        afrag[kc * 4 + 2] = *reinterpret_cast<const uint32_t*>(&sh_h[base + 8]);
        afrag[kc * 4 + 3] = *reinterpret_cast<const uint32_t*>(&sh_h[base + 8 * HSTR2 + 8]);
    }

    const float* Bs[3] = {bq, bk, bv};
    __half*      Os[3] = {g_qh, g_kh, g_vh};
    const float  Ss[3] = {0.25f, 1.0f, 1.0f};

    const int orow0 = node0 + m0 + (lane >> 2);
    const int ocol  = (lane & 3) * 2;

    for (int g = 0; g < 3; g++) {
        const float* bias  = Bs[g];
        __half*      out   = Os[g];
        const float  scale = Ss[g];

#pragma unroll
        for (int np = 0; np < 8; np++) {
            float acc0[4] = {0.f, 0.f, 0.f, 0.f};
            float acc1[4] = {0.f, 0.f, 0.f, 0.f};
            const uint4* wp = &g_wbh[((g * 8 + np) * 8) * 32 + lane];
#pragma unroll
            for (int kc = 0; kc < 8; kc++) {
                const uint4 b = wp[kc * 32];
                mma_f16(acc0, &afrag[kc * 4], b.x, b.y);
                mma_f16(acc1, &afrag[kc * 4], b.z, b.w);
            }
            const int c00 = np * 16 + ocol;
            const float bx0 = __ldg(&bias[c00]),     by0 = __ldg(&bias[c00 + 1]);
            const float bx1 = __ldg(&bias[c00 + 8]), by1 = __ldg(&bias[c00 + 9]);
            if (orow0 < N) {
                __half2* p = reinterpret_cast<__half2*>(&out[orow0 * HIDDEN + c00]);
                p[0] = __floats2half2_rn((acc0[0] + bx0) * scale, (acc0[1] + by0) * scale);
                p[4] = __floats2half2_rn((acc1[0] + bx1) * scale, (acc1[1] + by1) * scale);
            }
            if (orow0 + 8 < N) {
                __half2* p = reinterpret_cast<__half2*>(&out[(orow0 + 8) * HIDDEN + c00]);
                p[0] = __floats2half2_rn((acc0[2] + bx0) * scale, (acc0[3] + by0) * scale);
                p[4] = __floats2half2_rn((acc1[2] + bx1) * scale, (acc1[3] + by1) * scale);
            }
        }
    }
}

// ---------------------------------------------------------------------------
// Attention: one warp per node, two passes, fp16 q/k/v.
// ---------------------------------------------------------------------------
__global__ __launch_bounds__(256) void k_attn(
    const int*           __restrict__ nbr_idx,
    const unsigned char* __restrict__ nbr_mask,
    float*               __restrict__ out, int N)
{
    const int warp = (blockIdx.x * blockDim.x + threadIdx.x) >> 5;
    const int lane = threadIdx.x & 31;
    if (warp >= N) return;
    const int n = warp;

    const int mask_i32 = g_mask_i32;

    int      jreg = 0;
    unsigned mreg = 0;
    if (lane < 16) {
        jreg = nbr_idx[n * 16 + lane];
        mreg = mask_i32
             ? (unsigned)reinterpret_cast<const int*>(nbr_mask)[n * 16 + lane]
             : (unsigned)nbr_mask[n * 16 + lane];
    }

    const uint2 qr = *reinterpret_cast<const uint2*>(&g_qh[n * HIDDEN + lane * 4]);
    const float2 q01 = __half22float2(*reinterpret_cast<const __half2*>(&qr.x));
    const float2 q23 = __half22float2(*reinterpret_cast<const __half2*>(&qr.y));

    // Pass 1: scores (fp16 k gather, 8B per lane).
    float sc[16];
#pragma unroll
    for (int kk = 0; kk < 16; kk++) {
        const int      j = __shfl_sync(0xffffffffu, jreg, kk);
        const unsigned m = __shfl_sync(0xffffffffu, mreg, kk);
        const uint2 kr = *reinterpret_cast<const uint2*>(&g_kh[j * HIDDEN + lane * 4]);
        const float2 k01 = __half22float2(*reinterpret_cast<const __half2*>(&kr.x));
        const float2 k23 = __half22float2(*reinterpret_cast<const __half2*>(&kr.y));
        float d = q01.x * k01.x + q01.y * k01.y + q23.x * k23.x + q23.y * k23.y;
        d += __shfl_xor_sync(0xffffffffu, d, 1);
        d += __shfl_xor_sync(0xffffffffu, d, 2);
        sc[kk] = m ? d : -1e9f;
    }

    // Softmax over 16 neighbors (per head; replicated in each 4-lane group).
    float mx = -1e30f;
#pragma unroll
    for (int kk = 0; kk < 16; kk++) mx = fmaxf(mx, sc[kk]);
    float s = 0.f;
#pragma unroll
    for (int kk = 0; kk < 16; kk++) { sc[kk] = __expf(sc[kk] - mx); s += sc[kk]; }
    const float inv = 1.f / s;

    // Pass 2: AV (fp16 v gather).
    float4 acc = make_float4(0.f, 0.f, 0.f, 0.f);
#pragma unroll
    for (int kk = 0; kk < 16; kk++) {
        const int   j = __shfl_sync(0xffffffffu, jreg, kk);
        const float p = sc[kk] * inv;
        const uint2 vr = *reinterpret_cast<const uint2*>(&g_vh[j * HIDDEN + lane * 4]);
        const float2 v01 = __half22float2(*reinterpret_cast<const __half2*>(&vr.x));
        const float2 v23 = __half22float2(*reinterpret_cast<const __half2*>(&vr.y));
        acc.x = fmaf(p, v01.x, acc.x);
        acc.y = fmaf(p, v01.y, acc.y);
        acc.z = fmaf(p, v23.x, acc.z);
        acc.w = fmaf(p, v23.y, acc.w);
    }
    reinterpret_cast<float4*>(out)[n * 32 + lane] = acc;
}

// ---------------------------------------------------------------------------
// Launch
// ---------------------------------------------------------------------------
extern "C" void kernel_launch(void* const* d_in, const int* in_sizes, int n_in,
                              void* d_out, int out_size)
{
    const int*           X        = (const int*)d_in[0];
    const int*           nbr_idx  = (const int*)d_in[1];
    const unsigned char* nbr_mask = (const unsigned char*)d_in[2];
    const float*         emb      = (const float*)d_in[3];
    const float*         Wq       = (const float*)d_in[4];
    const float*         bq       = (const float*)d_in[5];
    const float*         Wk       = (const float*)d_in[6];
    const float*         bk       = (const float*)d_in[7];
    const float*         Wv       = (const float*)d_in[8];
    const float*         bv       = (const float*)d_in[9];
    float*               out      = (float*)d_out;

    const int N = in_sizes[0] / N_FEATS;

    k_prep<<<13, 512>>>(Wq, Wk, Wv, nbr_mask);

    const int smem_bytes = TILE_M * HSTR2 * 2 + TILE_M * N_FEATS * 4;  // ~39.4KB
    cudaFuncSetAttribute(k_encode_qkv,
                         cudaFuncAttributeMaxDynamicSharedMemorySize, smem_bytes);

    const int grid1 = (N + TILE_M - 1) / TILE_M;
    k_encode_qkv<<<grid1, 256, smem_bytes>>>(X, emb, bq, bk, bv, N);

    const int grid2 = (N + 7) / 8;
    k_attn<<<grid2, 256>>>(nbr_idx, nbr_mask, out, N);
}